// round 6
// baseline (speedup 1.0000x reference)
#include <cuda_runtime.h>
#include <math.h>

// Problem constants
constexpr int B_ = 2, N_ = 4096, E_ = 768, H_ = 8, D_ = 96;
constexpr int M_ = B_ * N_;          // 8192 rows for projection GEMMs
constexpr float SCALING_ = 9.797958971132712f;   // sqrt(96)

// Scratch (static device arrays; allocation APIs are forbidden)
__device__ float g_q[B_ * H_ * N_ * D_];    // [b,h,n,d]
__device__ float g_k[B_ * H_ * N_ * D_];
__device__ float g_v[B_ * H_ * N_ * D_];
__device__ float g_att[B_ * N_ * E_];       // merged-heads attention output [b,n,e]

// ---------------------------------------------------------------------------
// Projection GEMM: out = x @ W + b, W in {Wq,Wk,Wv} by blockIdx.z,
// written head-split into g_q/g_k/g_v as [b,h,n,d].
// 128x128 tile, BK=16, 256 threads, 8x8 per thread.
// B-operand per-thread cols split 4+4 at distance 64 -> conflict-free LDS.128.
// ---------------------------------------------------------------------------
__global__ __launch_bounds__(256) void qkv_gemm(
    const float* __restrict__ x,
    const float* __restrict__ Wq, const float* __restrict__ bq,
    const float* __restrict__ Wk, const float* __restrict__ bk,
    const float* __restrict__ Wv, const float* __restrict__ bv)
{
    const int which = blockIdx.z;
    const float* __restrict__ W    = (which == 0) ? Wq : (which == 1) ? Wk : Wv;
    const float* __restrict__ bias = (which == 0) ? bq : (which == 1) ? bk : bv;
    float* __restrict__ out        = (which == 0) ? g_q : (which == 1) ? g_k : g_v;

    __shared__ float Ast[16][136];   // [k][row]
    __shared__ float Bs[16][136];    // [k][col]

    const int rowStart = blockIdx.x * 128;
    const int colStart = blockIdx.y * 128;
    const int tid = threadIdx.x;
    const int ty = tid >> 4, tx = tid & 15;

    const int ar0 = tid >> 2,  akc = (tid & 3) * 4;    // A: row, k-offset
    const int bk0 = tid >> 5,  bc  = (tid & 31) * 4;   // B: k, col-offset

    float acc[8][8];
    #pragma unroll
    for (int i = 0; i < 8; i++)
        #pragma unroll
        for (int j = 0; j < 8; j++) acc[i][j] = 0.f;

    float4 aReg[2], bReg[2];
    #pragma unroll
    for (int l = 0; l < 2; l++) {
        aReg[l] = *(const float4*)&x[(rowStart + ar0 + l * 64) * E_ + akc];
        bReg[l] = *(const float4*)&W[(bk0 + l * 8) * E_ + colStart + bc];
    }

    for (int k0 = 0; k0 < E_; k0 += 16) {
        #pragma unroll
        for (int l = 0; l < 2; l++) {
            int r = ar0 + l * 64;
            Ast[akc + 0][r] = aReg[l].x;
            Ast[akc + 1][r] = aReg[l].y;
            Ast[akc + 2][r] = aReg[l].z;
            Ast[akc + 3][r] = aReg[l].w;
            *(float4*)&Bs[bk0 + l * 8][bc] = bReg[l];
        }
        __syncthreads();

        if (k0 + 16 < E_) {
            #pragma unroll
            for (int l = 0; l < 2; l++) {
                aReg[l] = *(const float4*)&x[(rowStart + ar0 + l * 64) * E_ + k0 + 16 + akc];
                bReg[l] = *(const float4*)&W[(k0 + 16 + bk0 + l * 8) * E_ + colStart + bc];
            }
        }

        #pragma unroll
        for (int k = 0; k < 16; k++) {
            float4 a0 = *(const float4*)&Ast[k][ty * 8];         // broadcast
            float4 a1 = *(const float4*)&Ast[k][ty * 8 + 4];
            float4 b0 = *(const float4*)&Bs[k][tx * 4];          // tx mod 8 banks
            float4 b1 = *(const float4*)&Bs[k][64 + tx * 4];
            float a[8] = {a0.x, a0.y, a0.z, a0.w, a1.x, a1.y, a1.z, a1.w};
            float b[8] = {b0.x, b0.y, b0.z, b0.w, b1.x, b1.y, b1.z, b1.w};
            #pragma unroll
            for (int i = 0; i < 8; i++)
                #pragma unroll
                for (int j = 0; j < 8; j++) acc[i][j] = fmaf(a[i], b[j], acc[i][j]);
        }
        __syncthreads();
    }

    // Epilogue: add bias, write head-split [b,h,n,d].
    // Thread cols: j4=0 -> colStart+tx*4+jj ; j4=1 -> colStart+64+tx*4+jj.
    // 4-col groups are 4-aligned; 96 % 4 == 0 so a group never crosses a head.
    #pragma unroll
    for (int i = 0; i < 8; i++) {
        int m = rowStart + ty * 8 + i;
        int bb = m / N_, nn = m % N_;
        #pragma unroll
        for (int j4 = 0; j4 < 2; j4++) {
            #pragma unroll
            for (int jj = 0; jj < 4; jj++) {
                int col = colStart + j4 * 64 + tx * 4 + jj;
                int hh = col / D_, dd = col % D_;
                out[((bb * H_ + hh) * N_ + nn) * D_ + dd] = acc[i][j4 * 4 + jj] + bias[col];
            }
        }
    }
}

// ---------------------------------------------------------------------------
// Flash attention: per (b,h), streaming softmax over K/V tiles.
// BM=64 query rows, BN=64 key rows per tile, 256 threads, 3 CTAs/SM.
// S-phase mapping: thread (ty,tx) computes rows ty*4+i, cols j*16+tx
//   -> K-operand LDS.128 conflict-free (adjacent lanes hit adjacent rows).
// Post-softmax /sqrt(96) folded into the final 1/l normalization.
// ---------------------------------------------------------------------------
constexpr int BM = 64, BN = 64;
constexpr int QSTR = 100;   // Q/K/V padded stride (25 float4 units, odd)
constexpr int SSTR = 68;    // score-tile stride (17 float4 units, odd)
constexpr int SMEM_FLASH = (BM * QSTR + BN * QSTR + BM * SSTR) * (int)sizeof(float);

__global__ __launch_bounds__(256, 3) void flash_attn()
{
    const int bh = blockIdx.y;               // 0..15
    const int qStart = blockIdx.x * BM;
    const float* __restrict__ Q = g_q + (size_t)bh * N_ * D_;
    const float* __restrict__ K = g_k + (size_t)bh * N_ * D_;
    const float* __restrict__ V = g_v + (size_t)bh * N_ * D_;

    extern __shared__ float sh[];
    float* Qs  = sh;                  // [64][100]
    float* KVs = Qs + BM * QSTR;      // [64][100], K then V (reused)
    float* Ss  = KVs + BN * QSTR;     // [64][68]

    const int tid = threadIdx.x;
    const int ty = tid >> 4, tx = tid & 15;    // S-phase: rows ty*4+i, cols j*16+tx
    const int r  = tid >> 2, l4 = tid & 3;     // row-phase: 64 rows x 4 lanes
    const int c0 = l4 * 24;                    // this thread's 24 output cols

    // Load Q tile once (float4, coalesced)
    for (int idx = tid; idx < BM * (D_ / 4); idx += 256) {
        int rr = idx / (D_ / 4), c4 = idx % (D_ / 4);
        *(float4*)&Qs[rr * QSTR + c4 * 4] =
            *(const float4*)&Q[(qStart + rr) * D_ + c4 * 4];
    }

    float O[24];
    #pragma unroll
    for (int i = 0; i < 24; i++) O[i] = 0.f;
    float m_run = -INFINITY, l_run = 0.f;

    float* srow = &Ss[r * SSTR];     // this thread's softmax row base

    for (int kt = 0; kt < N_ / BN; kt++) {
        const float* Kt = K + (size_t)kt * BN * D_;
        const float* Vt = V + (size_t)kt * BN * D_;

        __syncthreads();  // previous AV phase done reading KVs
        for (int idx = tid; idx < BN * (D_ / 4); idx += 256) {
            int rr = idx / (D_ / 4), c4 = idx % (D_ / 4);
            *(float4*)&KVs[rr * QSTR + c4 * 4] =
                *(const float4*)&Kt[rr * D_ + c4 * 4];
        }
        __syncthreads();

        // S = Q @ K^T: rows ty*4+i, cols j*16+tx (conflict-free K loads)
        float s[4][4];
        #pragma unroll
        for (int i = 0; i < 4; i++)
            #pragma unroll
            for (int j = 0; j < 4; j++) s[i][j] = 0.f;
        #pragma unroll 4
        for (int k = 0; k < D_; k += 4) {
            float4 qv[4], kv[4];
            #pragma unroll
            for (int i = 0; i < 4; i++)
                qv[i] = *(const float4*)&Qs[(ty * 4 + i) * QSTR + k];
            #pragma unroll
            for (int j = 0; j < 4; j++)
                kv[j] = *(const float4*)&KVs[(j * 16 + tx) * QSTR + k];
            #pragma unroll
            for (int i = 0; i < 4; i++)
                #pragma unroll
                for (int j = 0; j < 4; j++) {
                    s[i][j] = fmaf(qv[i].x, kv[j].x, s[i][j]);
                    s[i][j] = fmaf(qv[i].y, kv[j].y, s[i][j]);
                    s[i][j] = fmaf(qv[i].z, kv[j].z, s[i][j]);
                    s[i][j] = fmaf(qv[i].w, kv[j].w, s[i][j]);
                }
        }
        // Scalar stores, cols strided 16: addresses distinct mod 32 -> conflict-free
        #pragma unroll
        for (int i = 0; i < 4; i++)
            #pragma unroll
            for (int j = 0; j < 4; j++)
                Ss[(ty * 4 + i) * SSTR + j * 16 + tx] = s[i][j];
        __syncthreads();   // S visible; KVs reads done

        // Load V tile (overwrites K) while doing row softmax on Ss
        for (int idx = tid; idx < BN * (D_ / 4); idx += 256) {
            int rr = idx / (D_ / 4), c4 = idx % (D_ / 4);
            *(float4*)&KVs[rr * QSTR + c4 * 4] =
                *(const float4*)&Vt[rr * D_ + c4 * 4];
        }

        // Online softmax, 4 threads per row
        float mx = -INFINITY;
        #pragma unroll
        for (int c = l4; c < BN; c += 4) mx = fmaxf(mx, srow[c]);
        mx = fmaxf(mx, __shfl_xor_sync(0xffffffffu, mx, 1));
        mx = fmaxf(mx, __shfl_xor_sync(0xffffffffu, mx, 2));
        float m_new = fmaxf(m_run, mx);
        float alpha = __expf(m_run - m_new);
        float psum = 0.f;
        #pragma unroll
        for (int c = l4; c < BN; c += 4) {
            float p = __expf(srow[c] - m_new);
            srow[c] = p;
            psum += p;
        }
        psum += __shfl_xor_sync(0xffffffffu, psum, 1);
        psum += __shfl_xor_sync(0xffffffffu, psum, 2);
        l_run = l_run * alpha + psum;
        m_run = m_new;
        __syncthreads();   // p + V tile visible

        // O = alpha*O + P @ V  (row r, cols [c0, c0+24)); p fetched 4-wide
        #pragma unroll
        for (int i = 0; i < 24; i++) O[i] *= alpha;
        #pragma unroll
        for (int k4 = 0; k4 < BN; k4 += 4) {
            float4 p4 = *(const float4*)&srow[k4];
            float pv[4] = {p4.x, p4.y, p4.z, p4.w};
            #pragma unroll
            for (int kk = 0; kk < 4; kk++) {
                float p = pv[kk];
                const float* vrow = &KVs[(k4 + kk) * QSTR + c0];
                #pragma unroll
                for (int i4 = 0; i4 < 6; i4++) {
                    float4 vv = *(const float4*)&vrow[i4 * 4];
                    O[i4 * 4 + 0] = fmaf(p, vv.x, O[i4 * 4 + 0]);
                    O[i4 * 4 + 1] = fmaf(p, vv.y, O[i4 * 4 + 1]);
                    O[i4 * 4 + 2] = fmaf(p, vv.z, O[i4 * 4 + 2]);
                    O[i4 * 4 + 3] = fmaf(p, vv.w, O[i4 * 4 + 3]);
                }
            }
        }
    }

    // Epilogue: O / (l * sqrt(D)), merge heads into [b,n,e], float4 stores
    const float inv = 1.0f / (l_run * SCALING_);
    const int bb = bh / H_, hh = bh % H_;
    float* dst = g_att + ((size_t)bb * N_ + qStart + r) * E_ + hh * D_ + c0;
    #pragma unroll
    for (int i4 = 0; i4 < 6; i4++) {
        float4 o4 = make_float4(O[i4 * 4 + 0] * inv, O[i4 * 4 + 1] * inv,
                                O[i4 * 4 + 2] * inv, O[i4 * 4 + 3] * inv);
        *(float4*)&dst[i4 * 4] = o4;
    }
}

// ---------------------------------------------------------------------------
// Output projection: d_out = g_att @ Wo + bo (same GEMM structure, plain write)
// ---------------------------------------------------------------------------
__global__ __launch_bounds__(256) void out_gemm(
    const float* __restrict__ W, const float* __restrict__ bias,
    float* __restrict__ C)
{
    __shared__ float Ast[16][136];
    __shared__ float Bs[16][136];

    const int rowStart = blockIdx.x * 128;
    const int colStart = blockIdx.y * 128;
    const int tid = threadIdx.x;
    const int ty = tid >> 4, tx = tid & 15;

    const int ar0 = tid >> 2,  akc = (tid & 3) * 4;
    const int bk0 = tid >> 5,  bc  = (tid & 31) * 4;

    float acc[8][8];
    #pragma unroll
    for (int i = 0; i < 8; i++)
        #pragma unroll
        for (int j = 0; j < 8; j++) acc[i][j] = 0.f;

    float4 aReg[2], bReg[2];
    #pragma unroll
    for (int l = 0; l < 2; l++) {
        aReg[l] = *(const float4*)&g_att[(size_t)(rowStart + ar0 + l * 64) * E_ + akc];
        bReg[l] = *(const float4*)&W[(bk0 + l * 8) * E_ + colStart + bc];
    }

    for (int k0 = 0; k0 < E_; k0 += 16) {
        #pragma unroll
        for (int l = 0; l < 2; l++) {
            int r = ar0 + l * 64;
            Ast[akc + 0][r] = aReg[l].x;
            Ast[akc + 1][r] = aReg[l].y;
            Ast[akc + 2][r] = aReg[l].z;
            Ast[akc + 3][r] = aReg[l].w;
            *(float4*)&Bs[bk0 + l * 8][bc] = bReg[l];
        }
        __syncthreads();

        if (k0 + 16 < E_) {
            #pragma unroll
            for (int l = 0; l < 2; l++) {
                aReg[l] = *(const float4*)&g_att[(size_t)(rowStart + ar0 + l * 64) * E_ + k0 + 16 + akc];
                bReg[l] = *(const float4*)&W[(k0 + 16 + bk0 + l * 8) * E_ + colStart + bc];
            }
        }

        #pragma unroll
        for (int k = 0; k < 16; k++) {
            float4 a0 = *(const float4*)&Ast[k][ty * 8];
            float4 a1 = *(const float4*)&Ast[k][ty * 8 + 4];
            float4 b0 = *(const float4*)&Bs[k][tx * 4];
            float4 b1 = *(const float4*)&Bs[k][64 + tx * 4];
            float a[8] = {a0.x, a0.y, a0.z, a0.w, a1.x, a1.y, a1.z, a1.w};
            float b[8] = {b0.x, b0.y, b0.z, b0.w, b1.x, b1.y, b1.z, b1.w};
            #pragma unroll
            for (int i = 0; i < 8; i++)
                #pragma unroll
                for (int j = 0; j < 8; j++) acc[i][j] = fmaf(a[i], b[j], acc[i][j]);
        }
        __syncthreads();
    }

    #pragma unroll
    for (int i = 0; i < 8; i++) {
        int m = rowStart + ty * 8 + i;
        #pragma unroll
        for (int j4 = 0; j4 < 2; j4++) {
            int col = colStart + j4 * 64 + tx * 4;
            float4 o4 = make_float4(acc[i][j4 * 4 + 0] + bias[col + 0],
                                    acc[i][j4 * 4 + 1] + bias[col + 1],
                                    acc[i][j4 * 4 + 2] + bias[col + 2],
                                    acc[i][j4 * 4 + 3] + bias[col + 3]);
            *(float4*)&C[(size_t)m * E_ + col] = o4;
        }
    }
}

// ---------------------------------------------------------------------------
extern "C" void kernel_launch(void* const* d_in, const int* in_sizes, int n_in,
                              void* d_out, int out_size)
{
    const float* x  = (const float*)d_in[0];
    const float* Wq = (const float*)d_in[1];
    const float* bq = (const float*)d_in[2];
    const float* Wk = (const float*)d_in[3];
    const float* bk = (const float*)d_in[4];
    const float* Wv = (const float*)d_in[5];
    const float* bv = (const float*)d_in[6];
    const float* Wo = (const float*)d_in[7];
    const float* bo = (const float*)d_in[8];
    float* out = (float*)d_out;

    // QKV projections: grid (8192/128, 768/128, 3)
    dim3 gQKV(M_ / 128, E_ / 128, 3);
    qkv_gemm<<<gQKV, 256>>>(x, Wq, bq, Wk, bk, Wv, bv);

    // Flash attention: grid (4096/64, B*H). Attr call is idempotent + capture-safe.
    cudaFuncSetAttribute(flash_attn, cudaFuncAttributeMaxDynamicSharedMemorySize,
                         SMEM_FLASH);
    dim3 gF(N_ / BM, B_ * H_);
    flash_attn<<<gF, 256, SMEM_FLASH>>>();

    // Output projection
    dim3 gO(M_ / 128, E_ / 128);
    out_gemm<<<gO, 256>>>(Wo, bo, out);
}

// round 9
// speedup vs baseline: 2.9029x; 2.9029x over previous
#include <cuda_runtime.h>
#include <cuda_bf16.h>
#include <stdint.h>
#include <math.h>

// Problem constants
constexpr int B_ = 2, N_ = 4096, E_ = 768, H_ = 8, D_ = 96;
constexpr int M_ = B_ * N_;
constexpr float SCALING_ = 9.797958971132712f;   // sqrt(96)

// Scratch: Q/K/V in split-bf16 (hi + lo) head-split [b,h,n,d]; attention out f32.
__device__ __nv_bfloat16 g_q_hi[B_ * H_ * N_ * D_];
__device__ __nv_bfloat16 g_q_lo[B_ * H_ * N_ * D_];
__device__ __nv_bfloat16 g_k_hi[B_ * H_ * N_ * D_];
__device__ __nv_bfloat16 g_k_lo[B_ * H_ * N_ * D_];
__device__ __nv_bfloat16 g_v_hi[B_ * H_ * N_ * D_];
__device__ __nv_bfloat16 g_v_lo[B_ * H_ * N_ * D_];
__device__ float g_att[B_ * N_ * E_];

// ---------------------------------------------------------------------------
// MMA / ldmatrix / cp.async helpers
// ---------------------------------------------------------------------------
__device__ __forceinline__ uint32_t smem_u32(const void* p) {
    return (uint32_t)__cvta_generic_to_shared(p);
}
__device__ __forceinline__ void ldsm_x4(uint32_t* r, uint32_t addr) {
    asm volatile("ldmatrix.sync.aligned.m8n8.x4.shared.b16 {%0,%1,%2,%3}, [%4];"
                 : "=r"(r[0]), "=r"(r[1]), "=r"(r[2]), "=r"(r[3]) : "r"(addr));
}
__device__ __forceinline__ void ldsm_x4_t(uint32_t* r, uint32_t addr) {
    asm volatile("ldmatrix.sync.aligned.m8n8.x4.trans.shared.b16 {%0,%1,%2,%3}, [%4];"
                 : "=r"(r[0]), "=r"(r[1]), "=r"(r[2]), "=r"(r[3]) : "r"(addr));
}
__device__ __forceinline__ void mma16816(float* c, const uint32_t* a,
                                         uint32_t b0, uint32_t b1) {
    asm volatile(
        "mma.sync.aligned.m16n8k16.row.col.f32.bf16.bf16.f32 "
        "{%0,%1,%2,%3},{%4,%5,%6,%7},{%8,%9},{%0,%1,%2,%3};"
        : "+f"(c[0]), "+f"(c[1]), "+f"(c[2]), "+f"(c[3])
        : "r"(a[0]), "r"(a[1]), "r"(a[2]), "r"(a[3]), "r"(b0), "r"(b1));
}
__device__ __forceinline__ void cp16(uint32_t dst, const void* src) {
    asm volatile("cp.async.cg.shared.global [%0], [%1], 16;" :: "r"(dst), "l"(src));
}
__device__ __forceinline__ void cp_commit() {
    asm volatile("cp.async.commit_group;");
}
// Split (x0,x1) into packed bf16x2 hi + lo residual.
__device__ __forceinline__ void split2(float x0, float x1, uint32_t& h, uint32_t& l) {
    __nv_bfloat162 hh = __floats2bfloat162_rn(x0, x1);
    h = *reinterpret_cast<uint32_t*>(&hh);
    float f0 = __low2float(hh), f1 = __high2float(hh);
    __nv_bfloat162 ll = __floats2bfloat162_rn(x0 - f0, x1 - f1);
    l = *reinterpret_cast<uint32_t*>(&ll);
}

// ---------------------------------------------------------------------------
// Projection GEMM: out = x @ W + b -> split-bf16 head-split [b,h,n,d].
// ---------------------------------------------------------------------------
__global__ __launch_bounds__(256) void qkv_gemm(
    const float* __restrict__ x,
    const float* __restrict__ Wq, const float* __restrict__ bq,
    const float* __restrict__ Wk, const float* __restrict__ bk,
    const float* __restrict__ Wv, const float* __restrict__ bv)
{
    const int which = blockIdx.z;
    const float* __restrict__ W    = (which == 0) ? Wq : (which == 1) ? Wk : Wv;
    const float* __restrict__ bias = (which == 0) ? bq : (which == 1) ? bk : bv;
    __nv_bfloat16* __restrict__ oh = (which == 0) ? g_q_hi : (which == 1) ? g_k_hi : g_v_hi;
    __nv_bfloat16* __restrict__ ol = (which == 0) ? g_q_lo : (which == 1) ? g_k_lo : g_v_lo;

    __shared__ float Ast[16][136];
    __shared__ float Bs[16][136];

    const int rowStart = blockIdx.x * 128;
    const int colStart = blockIdx.y * 128;
    const int tid = threadIdx.x;
    const int ty = tid >> 4, tx = tid & 15;
    const int ar0 = tid >> 2, akc = (tid & 3) * 4;
    const int bk0 = tid >> 5, bc  = (tid & 31) * 4;

    float acc[8][8];
    #pragma unroll
    for (int i = 0; i < 8; i++)
        #pragma unroll
        for (int j = 0; j < 8; j++) acc[i][j] = 0.f;

    float4 aReg[2], bReg[2];
    #pragma unroll
    for (int l = 0; l < 2; l++) {
        aReg[l] = *(const float4*)&x[(rowStart + ar0 + l * 64) * E_ + akc];
        bReg[l] = *(const float4*)&W[(bk0 + l * 8) * E_ + colStart + bc];
    }

    for (int k0 = 0; k0 < E_; k0 += 16) {
        #pragma unroll
        for (int l = 0; l < 2; l++) {
            int r = ar0 + l * 64;
            Ast[akc + 0][r] = aReg[l].x;
            Ast[akc + 1][r] = aReg[l].y;
            Ast[akc + 2][r] = aReg[l].z;
            Ast[akc + 3][r] = aReg[l].w;
            *(float4*)&Bs[bk0 + l * 8][bc] = bReg[l];
        }
        __syncthreads();
        if (k0 + 16 < E_) {
            #pragma unroll
            for (int l = 0; l < 2; l++) {
                aReg[l] = *(const float4*)&x[(rowStart + ar0 + l * 64) * E_ + k0 + 16 + akc];
                bReg[l] = *(const float4*)&W[(k0 + 16 + bk0 + l * 8) * E_ + colStart + bc];
            }
        }
        #pragma unroll
        for (int k = 0; k < 16; k++) {
            float4 a0 = *(const float4*)&Ast[k][ty * 8];
            float4 a1 = *(const float4*)&Ast[k][ty * 8 + 4];
            float4 b0 = *(const float4*)&Bs[k][tx * 4];
            float4 b1 = *(const float4*)&Bs[k][64 + tx * 4];
            float a[8] = {a0.x, a0.y, a0.z, a0.w, a1.x, a1.y, a1.z, a1.w};
            float b[8] = {b0.x, b0.y, b0.z, b0.w, b1.x, b1.y, b1.z, b1.w};
            #pragma unroll
            for (int i = 0; i < 8; i++)
                #pragma unroll
                for (int j = 0; j < 8; j++) acc[i][j] = fmaf(a[i], b[j], acc[i][j]);
        }
        __syncthreads();
    }

    // Epilogue: bias add, bf16 hi/lo split, packed 2-wide head-split stores.
    // Col groups are 4-aligned; D=96 even -> bf16x2 pairs stay inside one head.
    #pragma unroll
    for (int i = 0; i < 8; i++) {
        int m = rowStart + ty * 8 + i;
        int bb = m / N_, nn = m % N_;
        #pragma unroll
        for (int j4 = 0; j4 < 2; j4++) {
            int col = colStart + j4 * 64 + tx * 4;
            float4 bi = *(const float4*)&bias[col];
            float v0 = acc[i][j4 * 4 + 0] + bi.x;
            float v1 = acc[i][j4 * 4 + 1] + bi.y;
            float v2 = acc[i][j4 * 4 + 2] + bi.z;
            float v3 = acc[i][j4 * 4 + 3] + bi.w;
            int hh = col / D_, dd = col % D_;
            size_t o = ((size_t)(bb * H_ + hh) * N_ + nn) * D_ + dd;
            uint32_t h01, l01, h23, l23;
            split2(v0, v1, h01, l01);
            split2(v2, v3, h23, l23);
            *(uint32_t*)&oh[o]     = h01;
            *(uint32_t*)&oh[o + 2] = h23;
            *(uint32_t*)&ol[o]     = l01;
            *(uint32_t*)&ol[o + 2] = l23;
        }
    }
}

// ---------------------------------------------------------------------------
// Flash attention on tensor pipe: bf16-split 3-MMA, cp.async double-buffered KV.
// BM=128 rows/CTA (8 warps x 16 rows), BN=64 kv tile. Softmax in registers.
// ---------------------------------------------------------------------------
constexpr int FM = 128, FN = 64;
constexpr int KSTR = 104;   // bf16 stride: 13 x 16B units (odd) -> ldmatrix conflict-free
constexpr int KVBUF = FN * KSTR;   // one K-or-V hi-or-lo buffer (bf16 elems)
constexpr int SMEM_MMA = (FM * 2 * KSTR + 2 * 4 * KVBUF) * 2;

__global__ __launch_bounds__(256) void flash_attn_mma()
{
    const int bh = blockIdx.y;
    const int qStart = blockIdx.x * FM;
    const size_t base = (size_t)bh * N_ * D_;
    const __nv_bfloat16* __restrict__ Qh = g_q_hi + base;
    const __nv_bfloat16* __restrict__ Ql = g_q_lo + base;
    const __nv_bfloat16* __restrict__ Kh = g_k_hi + base;
    const __nv_bfloat16* __restrict__ Kl = g_k_lo + base;
    const __nv_bfloat16* __restrict__ Vh = g_v_hi + base;
    const __nv_bfloat16* __restrict__ Vl = g_v_lo + base;

    extern __shared__ __nv_bfloat16 sb[];
    __nv_bfloat16* Qhs = sb;
    __nv_bfloat16* Qls = Qhs + FM * KSTR;
    __nv_bfloat16* Khs = Qls + FM * KSTR;     // [2][KVBUF]
    __nv_bfloat16* Kls = Khs + 2 * KVBUF;
    __nv_bfloat16* Vhs = Kls + 2 * KVBUF;
    __nv_bfloat16* Vls = Vhs + 2 * KVBUF;

    const int tid = threadIdx.x;
    const int wid = tid >> 5, lane = tid & 31;
    const int lr = lane & 15, lc8 = (lane >> 4) * 8;

    const uint32_t qh_b = smem_u32(Qhs), ql_b = smem_u32(Qls);
    const uint32_t kh_b = smem_u32(Khs), kl_b = smem_u32(Kls);
    const uint32_t vh_b = smem_u32(Vhs), vl_b = smem_u32(Vls);

    auto issue_kv = [&](int kt, int buf) {
        const uint32_t sbase = (uint32_t)(buf * KVBUF * 2);
        for (int idx = tid; idx < FN * 12; idx += 256) {
            int rr = idx / 12, c8 = (idx % 12) * 8;
            const int src = (kt * FN + rr) * D_ + c8;
            const uint32_t doff = sbase + (rr * KSTR + c8) * 2;
            cp16(kh_b + doff, Kh + src);
            cp16(kl_b + doff, Kl + src);
            cp16(vh_b + doff, Vh + src);
            cp16(vl_b + doff, Vl + src);
        }
        cp_commit();
    };

    // Prologue: KV tile 0 in flight, then Q tile via regular loads.
    issue_kv(0, 0);
    for (int idx = tid; idx < FM * 12; idx += 256) {
        int rr = idx / 12, c8 = (idx % 12) * 8;
        *(uint4*)&Qhs[rr * KSTR + c8] = *(const uint4*)&Qh[(qStart + rr) * D_ + c8];
        *(uint4*)&Qls[rr * KSTR + c8] = *(const uint4*)&Ql[(qStart + rr) * D_ + c8];
    }

    float O[12][4];
    #pragma unroll
    for (int d = 0; d < 12; d++)
        #pragma unroll
        for (int e = 0; e < 4; e++) O[d][e] = 0.f;
    float m0 = -INFINITY, m1 = -INFINITY, l0 = 0.f, l1 = 0.f;

    const int qrow_off = (16 * wid + lr) * KSTR + lc8;
    constexpr int NT = N_ / FN;

    for (int kt = 0; kt < NT; kt++) {
        const int p = kt & 1;
        if (kt + 1 < NT) {
            issue_kv(kt + 1, 1 - p);
            asm volatile("cp.async.wait_group 1;");
        } else {
            asm volatile("cp.async.wait_group 0;");
        }
        __syncthreads();   // tile kt data (all threads' copies) visible

        const uint32_t kvoff = (uint32_t)(p * KVBUF * 2);

        // ---- S = Q K^T ----
        float sa[8][4];
        #pragma unroll
        for (int nt = 0; nt < 8; nt++)
            #pragma unroll
            for (int e = 0; e < 4; e++) sa[nt][e] = 0.f;

        #pragma unroll
        for (int kc = 0; kc < 6; kc++) {
            uint32_t qa[4], qb[4];
            ldsm_x4(qa, qh_b + (qrow_off + kc * 16) * 2);
            ldsm_x4(qb, ql_b + (qrow_off + kc * 16) * 2);
            #pragma unroll
            for (int np = 0; np < 4; np++) {
                const uint32_t koff = kvoff + ((np * 16 + lr) * KSTR + kc * 16 + lc8) * 2;
                uint32_t ka[4], kb[4];
                ldsm_x4(ka, kh_b + koff);
                ldsm_x4(kb, kl_b + koff);
                mma16816(sa[2 * np],     qa, ka[0], ka[2]);
                mma16816(sa[2 * np],     qa, kb[0], kb[2]);
                mma16816(sa[2 * np],     qb, ka[0], ka[2]);
                mma16816(sa[2 * np + 1], qa, ka[1], ka[3]);
                mma16816(sa[2 * np + 1], qa, kb[1], kb[3]);
                mma16816(sa[2 * np + 1], qb, ka[1], ka[3]);
            }
        }

        // ---- online softmax ----
        float mx0 = -INFINITY, mx1 = -INFINITY;
        #pragma unroll
        for (int nt = 0; nt < 8; nt++) {
            mx0 = fmaxf(mx0, fmaxf(sa[nt][0], sa[nt][1]));
            mx1 = fmaxf(mx1, fmaxf(sa[nt][2], sa[nt][3]));
        }
        mx0 = fmaxf(mx0, __shfl_xor_sync(0xffffffffu, mx0, 1));
        mx0 = fmaxf(mx0, __shfl_xor_sync(0xffffffffu, mx0, 2));
        mx1 = fmaxf(mx1, __shfl_xor_sync(0xffffffffu, mx1, 1));
        mx1 = fmaxf(mx1, __shfl_xor_sync(0xffffffffu, mx1, 2));
        const float mn0 = fmaxf(m0, mx0), mn1 = fmaxf(m1, mx1);
        const float al0 = __expf(m0 - mn0), al1 = __expf(m1 - mn1);
        float ps0 = 0.f, ps1 = 0.f;
        #pragma unroll
        for (int nt = 0; nt < 8; nt++) {
            sa[nt][0] = __expf(sa[nt][0] - mn0); ps0 += sa[nt][0];
            sa[nt][1] = __expf(sa[nt][1] - mn0); ps0 += sa[nt][1];
            sa[nt][2] = __expf(sa[nt][2] - mn1); ps1 += sa[nt][2];
            sa[nt][3] = __expf(sa[nt][3] - mn1); ps1 += sa[nt][3];
        }
        ps0 += __shfl_xor_sync(0xffffffffu, ps0, 1);
        ps0 += __shfl_xor_sync(0xffffffffu, ps0, 2);
        ps1 += __shfl_xor_sync(0xffffffffu, ps1, 1);
        ps1 += __shfl_xor_sync(0xffffffffu, ps1, 2);
        l0 = l0 * al0 + ps0;  m0 = mn0;
        l1 = l1 * al1 + ps1;  m1 = mn1;
        #pragma unroll
        for (int d = 0; d < 12; d++) {
            O[d][0] *= al0;  O[d][1] *= al0;
            O[d][2] *= al1;  O[d][3] *= al1;
        }

        // ---- O += P V ----
        #pragma unroll
        for (int kc = 0; kc < 4; kc++) {
            uint32_t ah[4], alo[4];
            split2(sa[2 * kc][0],     sa[2 * kc][1],     ah[0], alo[0]);
            split2(sa[2 * kc][2],     sa[2 * kc][3],     ah[1], alo[1]);
            split2(sa[2 * kc + 1][0], sa[2 * kc + 1][1], ah[2], alo[2]);
            split2(sa[2 * kc + 1][2], sa[2 * kc + 1][3], ah[3], alo[3]);
            #pragma unroll
            for (int dp = 0; dp < 6; dp++) {
                const uint32_t voff = kvoff + ((kc * 16 + lr) * KSTR + dp * 16 + lc8) * 2;
                uint32_t va[4], vb[4];
                ldsm_x4_t(va, vh_b + voff);
                ldsm_x4_t(vb, vl_b + voff);
                mma16816(O[2 * dp],     ah,  va[0], va[1]);
                mma16816(O[2 * dp],     ah,  vb[0], vb[1]);
                mma16816(O[2 * dp],     alo, va[0], va[1]);
                mma16816(O[2 * dp + 1], ah,  va[2], va[3]);
                mma16816(O[2 * dp + 1], ah,  vb[2], vb[3]);
                mma16816(O[2 * dp + 1], alo, va[2], va[3]);
            }
        }
        __syncthreads();   // done reading buf p before kt+1 overwrites it
    }

    // ---- epilogue ----
    const float inv0 = 1.0f / (l0 * SCALING_);
    const float inv1 = 1.0f / (l1 * SCALING_);
    const int bb = bh >> 3, hh = bh & 7;
    const int r0g = qStart + 16 * wid + (lane >> 2);
    const int cbase = hh * D_ + 2 * (lane & 3);
    #pragma unroll
    for (int dt = 0; dt < 12; dt++) {
        const int c = cbase + dt * 8;
        float2 o0 = make_float2(O[dt][0] * inv0, O[dt][1] * inv0);
        float2 o1 = make_float2(O[dt][2] * inv1, O[dt][3] * inv1);
        *(float2*)&g_att[((size_t)bb * N_ + r0g) * E_ + c] = o0;
        *(float2*)&g_att[((size_t)bb * N_ + r0g + 8) * E_ + c] = o1;
    }
}

// ---------------------------------------------------------------------------
// Output projection: d_out = g_att @ Wo + bo (fp32)
// ---------------------------------------------------------------------------
__global__ __launch_bounds__(256) void out_gemm(
    const float* __restrict__ W, const float* __restrict__ bias,
    float* __restrict__ C)
{
    __shared__ float Ast[16][136];
    __shared__ float Bs[16][136];

    const int rowStart = blockIdx.x * 128;
    const int colStart = blockIdx.y * 128;
    const int tid = threadIdx.x;
    const int ty = tid >> 4, tx = tid & 15;
    const int ar0 = tid >> 2, akc = (tid & 3) * 4;
    const int bk0 = tid >> 5, bc  = (tid & 31) * 4;

    float acc[8][8];
    #pragma unroll
    for (int i = 0; i < 8; i++)
        #pragma unroll
        for (int j = 0; j < 8; j++) acc[i][j] = 0.f;

    float4 aReg[2], bReg[2];
    #pragma unroll
    for (int l = 0; l < 2; l++) {
        aReg[l] = *(const float4*)&g_att[(size_t)(rowStart + ar0 + l * 64) * E_ + akc];
        bReg[l] = *(const float4*)&W[(bk0 + l * 8) * E_ + colStart + bc];
    }

    for (int k0 = 0; k0 < E_; k0 += 16) {
        #pragma unroll
        for (int l = 0; l < 2; l++) {
            int r = ar0 + l * 64;
            Ast[akc + 0][r] = aReg[l].x;
            Ast[akc + 1][r] = aReg[l].y;
            Ast[akc + 2][r] = aReg[l].z;
            Ast[akc + 3][r] = aReg[l].w;
            *(float4*)&Bs[bk0 + l * 8][bc] = bReg[l];
        }
        __syncthreads();
        if (k0 + 16 < E_) {
            #pragma unroll
            for (int l = 0; l < 2; l++) {
                aReg[l] = *(const float4*)&g_att[(size_t)(rowStart + ar0 + l * 64) * E_ + k0 + 16 + akc];
                bReg[l] = *(const float4*)&W[(k0 + 16 + bk0 + l * 8) * E_ + colStart + bc];
            }
        }
        #pragma unroll
        for (int k = 0; k < 16; k++) {
            float4 a0 = *(const float4*)&Ast[k][ty * 8];
            float4 a1 = *(const float4*)&Ast[k][ty * 8 + 4];
            float4 b0 = *(const float4*)&Bs[k][tx * 4];
            float4 b1 = *(const float4*)&Bs[k][64 + tx * 4];
            float a[8] = {a0.x, a0.y, a0.z, a0.w, a1.x, a1.y, a1.z, a1.w};
            float b[8] = {b0.x, b0.y, b0.z, b0.w, b1.x, b1.y, b1.z, b1.w};
            #pragma unroll
            for (int i = 0; i < 8; i++)
                #pragma unroll
                for (int j = 0; j < 8; j++) acc[i][j] = fmaf(a[i], b[j], acc[i][j]);
        }
        __syncthreads();
    }

    #pragma unroll
    for (int i = 0; i < 8; i++) {
        int m = rowStart + ty * 8 + i;
        #pragma unroll
        for (int j4 = 0; j4 < 2; j4++) {
            int col = colStart + j4 * 64 + tx * 4;
            float4 o4 = make_float4(acc[i][j4 * 4 + 0] + bias[col + 0],
                                    acc[i][j4 * 4 + 1] + bias[col + 1],
                                    acc[i][j4 * 4 + 2] + bias[col + 2],
                                    acc[i][j4 * 4 + 3] + bias[col + 3]);
            *(float4*)&C[(size_t)m * E_ + col] = o4;
        }
    }
}

// ---------------------------------------------------------------------------
extern "C" void kernel_launch(void* const* d_in, const int* in_sizes, int n_in,
                              void* d_out, int out_size)
{
    const float* x  = (const float*)d_in[0];
    const float* Wq = (const float*)d_in[1];
    const float* bq = (const float*)d_in[2];
    const float* Wk = (const float*)d_in[3];
    const float* bk = (const float*)d_in[4];
    const float* Wv = (const float*)d_in[5];
    const float* bv = (const float*)d_in[6];
    const float* Wo = (const float*)d_in[7];
    const float* bo = (const float*)d_in[8];
    float* out = (float*)d_out;

    dim3 gQKV(M_ / 128, E_ / 128, 3);
    qkv_gemm<<<gQKV, 256>>>(x, Wq, bq, Wk, bk, Wv, bv);

    cudaFuncSetAttribute(flash_attn_mma, cudaFuncAttributeMaxDynamicSharedMemorySize,
                         SMEM_MMA);
    dim3 gF(N_ / FM, B_ * H_);
    flash_attn_mma<<<gF, 256, SMEM_MMA>>>();

    dim3 gO(M_ / 128, E_ / 128);
    out_gemm<<<gO, 256>>>(Wo, bo, out);
}

// round 16
// speedup vs baseline: 3.9504x; 1.3608x over previous
#include <cuda_runtime.h>
#include <cuda_bf16.h>
#include <stdint.h>
#include <math.h>

// Problem constants
constexpr int B_ = 2, N_ = 4096, E_ = 768, H_ = 8, D_ = 96;
constexpr int M_ = B_ * N_;
constexpr float SCALING_ = 9.797958971132712f;   // sqrt(96)

// Scratch (static device arrays)
__device__ __nv_bfloat16 g_x_hi[M_ * E_],  g_x_lo[M_ * E_];
__device__ __nv_bfloat16 g_wq_hi[E_ * E_], g_wq_lo[E_ * E_];
__device__ __nv_bfloat16 g_wk_hi[E_ * E_], g_wk_lo[E_ * E_];
__device__ __nv_bfloat16 g_wv_hi[E_ * E_], g_wv_lo[E_ * E_];
__device__ __nv_bfloat16 g_wo_hi[E_ * E_], g_wo_lo[E_ * E_];
__device__ __nv_bfloat16 g_q_hi[M_ * E_],  g_q_lo[M_ * E_];   // head-split [b,h,n,d]
__device__ __nv_bfloat16 g_k_hi[M_ * E_],  g_k_lo[M_ * E_];
__device__ __nv_bfloat16 g_v_hi[M_ * E_],  g_v_lo[M_ * E_];
__device__ __nv_bfloat16 g_att_hi[M_ * E_], g_att_lo[M_ * E_]; // merged [b,n,e]

// ---------------------------------------------------------------------------
// Helpers
// ---------------------------------------------------------------------------
__device__ __forceinline__ uint32_t smem_u32(const void* p) {
    return (uint32_t)__cvta_generic_to_shared(p);
}
__device__ __forceinline__ void ldsm_x4(uint32_t* r, uint32_t addr) {
    asm volatile("ldmatrix.sync.aligned.m8n8.x4.shared.b16 {%0,%1,%2,%3}, [%4];"
                 : "=r"(r[0]), "=r"(r[1]), "=r"(r[2]), "=r"(r[3]) : "r"(addr));
}
__device__ __forceinline__ void ldsm_x4_t(uint32_t* r, uint32_t addr) {
    asm volatile("ldmatrix.sync.aligned.m8n8.x4.trans.shared.b16 {%0,%1,%2,%3}, [%4];"
                 : "=r"(r[0]), "=r"(r[1]), "=r"(r[2]), "=r"(r[3]) : "r"(addr));
}
__device__ __forceinline__ void mma16816(float* c, const uint32_t* a,
                                         uint32_t b0, uint32_t b1) {
    asm volatile(
        "mma.sync.aligned.m16n8k16.row.col.f32.bf16.bf16.f32 "
        "{%0,%1,%2,%3},{%4,%5,%6,%7},{%8,%9},{%0,%1,%2,%3};"
        : "+f"(c[0]), "+f"(c[1]), "+f"(c[2]), "+f"(c[3])
        : "r"(a[0]), "r"(a[1]), "r"(a[2]), "r"(a[3]), "r"(b0), "r"(b1));
}
__device__ __forceinline__ void cp16(uint32_t dst, const void* src) {
    asm volatile("cp.async.cg.shared.global [%0], [%1], 16;" :: "r"(dst), "l"(src));
}
__device__ __forceinline__ void cp_commit() {
    asm volatile("cp.async.commit_group;");
}
__device__ __forceinline__ void split2(float x0, float x1, uint32_t& h, uint32_t& l) {
    __nv_bfloat162 hh = __floats2bfloat162_rn(x0, x1);
    h = *reinterpret_cast<uint32_t*>(&hh);
    float f0 = __low2float(hh), f1 = __high2float(hh);
    __nv_bfloat162 ll = __floats2bfloat162_rn(x0 - f0, x1 - f1);
    l = *reinterpret_cast<uint32_t*>(&ll);
}

// ---------------------------------------------------------------------------
// Elementwise split: f32 -> bf16 hi + lo
// ---------------------------------------------------------------------------
__global__ __launch_bounds__(256) void split_f32(
    const float* __restrict__ in, __nv_bfloat16* __restrict__ hi,
    __nv_bfloat16* __restrict__ lo, int n4)
{
    int i = blockIdx.x * 256 + threadIdx.x;
    if (i >= n4) return;
    float4 v = ((const float4*)in)[i];
    uint32_t h01, l01, h23, l23;
    split2(v.x, v.y, h01, l01);
    split2(v.z, v.w, h23, l23);
    ((uint32_t*)hi)[i * 2]     = h01;
    ((uint32_t*)hi)[i * 2 + 1] = h23;
    ((uint32_t*)lo)[i * 2]     = l01;
    ((uint32_t*)lo)[i * 2 + 1] = l23;
}

// ---------------------------------------------------------------------------
// bf16-split MMA GEMM: C = A @ W (+bias). A [M,768] hi/lo, W [768,768] hi/lo.
// CTA 128x128, BK=32, 8 warps (2m x 4n), warp tile 64x32. cp.async double-buf.
// MODE 0: head-split bf16 hi/lo scatter (+bias). MODE 1: f32 bias write.
// ---------------------------------------------------------------------------
constexpr int ABUF = 128 * 40;    // A tile elems per dtype per buffer (stride 40)
constexpr int WBUF = 32 * 136;    // W tile elems per dtype per buffer (stride 136)
constexpr int ASTR = 40, WSTR = 136;
constexpr int SMEM_GEMM = (4 * ABUF + 4 * WBUF) * 2;   // bytes

template <int MODE>
__device__ __forceinline__ void mma_gemm_body(
    const __nv_bfloat16* __restrict__ Ah, const __nv_bfloat16* __restrict__ Al,
    const __nv_bfloat16* __restrict__ Wh, const __nv_bfloat16* __restrict__ Wl,
    const float* __restrict__ bias,
    __nv_bfloat16* __restrict__ oh, __nv_bfloat16* __restrict__ ol,
    float* __restrict__ C)
{
    extern __shared__ __nv_bfloat16 sg[];
    __nv_bfloat16* Ahs = sg;                       // [2][ABUF]
    __nv_bfloat16* Als = Ahs + 2 * ABUF;
    __nv_bfloat16* Whs = Als + 2 * ABUF;           // [2][WBUF]
    __nv_bfloat16* Wls = Whs + 2 * WBUF;

    const int rowStart = blockIdx.x * 128;
    const int colStart = blockIdx.y * 128;
    const int tid = threadIdx.x;
    const int wid = tid >> 5, lane = tid & 31;
    const int lr = lane & 15, lc8 = (lane >> 4) * 8;
    const int wm = wid & 1, wn = wid >> 1;

    const uint32_t ah_b = smem_u32(Ahs), al_b = smem_u32(Als);
    const uint32_t wh_b = smem_u32(Whs), wl_b = smem_u32(Wls);

    // Per-thread copy indices (2 batches of: 1 A-row-chunk + 1 W-row-chunk)
    const int a_r0 = tid >> 2,        a_c0 = (tid & 3) * 8;
    const int a_r1 = (tid + 256) >> 2, a_c1 = ((tid + 256) & 3) * 8;
    const int w_r0 = tid >> 4,        w_c0 = (tid & 15) * 8;
    const int w_r1 = (tid + 256) >> 4, w_c1 = ((tid + 256) & 15) * 8;
    const uint32_t a_d0 = (a_r0 * ASTR + a_c0) * 2, a_d1 = (a_r1 * ASTR + a_c1) * 2;
    const uint32_t w_d0 = (w_r0 * WSTR + w_c0) * 2, w_d1 = (w_r1 * WSTR + w_c1) * 2;

    float acc[4][4][4];
    #pragma unroll
    for (int mt = 0; mt < 4; mt++)
        #pragma unroll
        for (int nt = 0; nt < 4; nt++)
            #pragma unroll
            for (int e = 0; e < 4; e++) acc[mt][nt][e] = 0.f;

    constexpr int NKS = E_ / 32;   // 24

    auto issue = [&](int ks, uint32_t abase, uint32_t wbase) {
        size_t asrc0 = (size_t)(rowStart + a_r0) * E_ + ks * 32 + a_c0;
        size_t asrc1 = (size_t)(rowStart + a_r1) * E_ + ks * 32 + a_c1;
        size_t wsrc0 = (size_t)(ks * 32 + w_r0) * E_ + colStart + w_c0;
        size_t wsrc1 = (size_t)(ks * 32 + w_r1) * E_ + colStart + w_c1;
        cp16(ah_b + abase + a_d0, Ah + asrc0);
        cp16(al_b + abase + a_d0, Al + asrc0);
        cp16(wh_b + wbase + w_d0, Wh + wsrc0);
        cp16(wl_b + wbase + w_d0, Wl + wsrc0);
        cp16(ah_b + abase + a_d1, Ah + asrc1);
        cp16(al_b + abase + a_d1, Al + asrc1);
        cp16(wh_b + wbase + w_d1, Wh + wsrc1);
        cp16(wl_b + wbase + w_d1, Wl + wsrc1);
        cp_commit();
    };

    issue(0, 0, 0);

    for (int ks = 0; ks < NKS; ks++) {
        const int p = ks & 1;
        if (ks + 1 < NKS) {
            issue(ks + 1, (uint32_t)((1 - p) * ABUF * 2), (uint32_t)((1 - p) * WBUF * 2));
            asm volatile("cp.async.wait_group 1;");
        } else {
            asm volatile("cp.async.wait_group 0;");
        }
        __syncthreads();

        const uint32_t aoffb = (uint32_t)(p * ABUF * 2);
        const uint32_t woffb = (uint32_t)(p * WBUF * 2);

        #pragma unroll
        for (int kc = 0; kc < 2; kc++) {
            uint32_t wh0[4], wh1[4], wl0[4], wl1[4];
            const uint32_t wrow = woffb + ((kc * 16 + lr) * WSTR + wn * 32 + lc8) * 2;
            ldsm_x4_t(wh0, wh_b + wrow);
            ldsm_x4_t(wh1, wh_b + wrow + 32);   // +16 cols * 2B
            ldsm_x4_t(wl0, wl_b + wrow);
            ldsm_x4_t(wl1, wl_b + wrow + 32);
            #pragma unroll
            for (int mt = 0; mt < 4; mt++) {
                uint32_t ah[4], al[4];
                const uint32_t arow = aoffb +
                    ((wm * 64 + mt * 16 + lr) * ASTR + kc * 16 + lc8) * 2;
                ldsm_x4(ah, ah_b + arow);
                ldsm_x4(al, al_b + arow);
                mma16816(acc[mt][0], ah, wh0[0], wh0[1]);
                mma16816(acc[mt][0], ah, wl0[0], wl0[1]);
                mma16816(acc[mt][0], al, wh0[0], wh0[1]);
                mma16816(acc[mt][1], ah, wh0[2], wh0[3]);
                mma16816(acc[mt][1], ah, wl0[2], wl0[3]);
                mma16816(acc[mt][1], al, wh0[2], wh0[3]);
                mma16816(acc[mt][2], ah, wh1[0], wh1[1]);
                mma16816(acc[mt][2], ah, wl1[0], wl1[1]);
                mma16816(acc[mt][2], al, wh1[0], wh1[1]);
                mma16816(acc[mt][3], ah, wh1[2], wh1[3]);
                mma16816(acc[mt][3], ah, wl1[2], wl1[3]);
                mma16816(acc[mt][3], al, wh1[2], wh1[3]);
            }
        }
        __syncthreads();
    }

    // Epilogue: acc[mt][nt][half*2+e] -> row wm*64+mt*16+lane/4+half*8,
    // col colStart + wn*32 + nt*8 + 2*(lane&3) + e.
    #pragma unroll
    for (int mt = 0; mt < 4; mt++) {
        #pragma unroll
        for (int half = 0; half < 2; half++) {
            int m = rowStart + wm * 64 + mt * 16 + (lane >> 2) + half * 8;
            #pragma unroll
            for (int nt = 0; nt < 4; nt++) {
                int col = colStart + wn * 32 + nt * 8 + 2 * (lane & 3);
                float2 bi = *(const float2*)&bias[col];
                float v0 = acc[mt][nt][half * 2]     + bi.x;
                float v1 = acc[mt][nt][half * 2 + 1] + bi.y;
                if (MODE == 0) {
                    int bb = m / N_, nn = m % N_;
                    int hh = col / D_, dd = col % D_;
                    size_t o = ((size_t)(bb * H_ + hh) * N_ + nn) * D_ + dd;
                    uint32_t h, l;
                    split2(v0, v1, h, l);
                    *(uint32_t*)&oh[o] = h;
                    *(uint32_t*)&ol[o] = l;
                } else {
                    float2 o2 = make_float2(v0, v1);
                    *(float2*)&C[(size_t)m * E_ + col] = o2;
                }
            }
        }
    }
}

// QKV: bias + bf16 hi/lo split + head-split scatter
__global__ __launch_bounds__(256) void qkv_mma(
    const float* __restrict__ bq, const float* __restrict__ bk,
    const float* __restrict__ bv)
{
    const int which = blockIdx.z;
    const __nv_bfloat16* Wh = (which == 0) ? g_wq_hi : (which == 1) ? g_wk_hi : g_wv_hi;
    const __nv_bfloat16* Wl = (which == 0) ? g_wq_lo : (which == 1) ? g_wk_lo : g_wv_lo;
    const float* bias = (which == 0) ? bq : (which == 1) ? bk : bv;
    __nv_bfloat16* oh = (which == 0) ? g_q_hi : (which == 1) ? g_k_hi : g_v_hi;
    __nv_bfloat16* ol = (which == 0) ? g_q_lo : (which == 1) ? g_k_lo : g_v_lo;

    mma_gemm_body<0>(g_x_hi, g_x_lo, Wh, Wl, bias, oh, ol, nullptr);
}

// Out-projection: bias + f32 write to d_out
__global__ __launch_bounds__(256) void out_mma(
    const float* __restrict__ bias, float* __restrict__ C)
{
    mma_gemm_body<1>(g_att_hi, g_att_lo, g_wo_hi, g_wo_lo, bias, nullptr, nullptr, C);
}

// ---------------------------------------------------------------------------
// Flash attention (validated R9 design); epilogue emits bf16 hi/lo g_att.
// ---------------------------------------------------------------------------
constexpr int FM = 128, FN = 64;
constexpr int KSTR = 104;
constexpr int KVBUF = FN * KSTR;
constexpr int SMEM_MMA = (FM * 2 * KSTR + 2 * 4 * KVBUF) * 2;

__global__ __launch_bounds__(256) void flash_attn_mma()
{
    const int bh = blockIdx.y;
    const int qStart = blockIdx.x * FM;
    const size_t base = (size_t)bh * N_ * D_;
    const __nv_bfloat16* __restrict__ Qh = g_q_hi + base;
    const __nv_bfloat16* __restrict__ Ql = g_q_lo + base;
    const __nv_bfloat16* __restrict__ Kh = g_k_hi + base;
    const __nv_bfloat16* __restrict__ Kl = g_k_lo + base;
    const __nv_bfloat16* __restrict__ Vh = g_v_hi + base;
    const __nv_bfloat16* __restrict__ Vl = g_v_lo + base;

    extern __shared__ __nv_bfloat16 sb[];
    __nv_bfloat16* Qhs = sb;
    __nv_bfloat16* Qls = Qhs + FM * KSTR;
    __nv_bfloat16* Khs = Qls + FM * KSTR;
    __nv_bfloat16* Kls = Khs + 2 * KVBUF;
    __nv_bfloat16* Vhs = Kls + 2 * KVBUF;
    __nv_bfloat16* Vls = Vhs + 2 * KVBUF;

    const int tid = threadIdx.x;
    const int wid = tid >> 5, lane = tid & 31;
    const int lr = lane & 15, lc8 = (lane >> 4) * 8;

    const uint32_t qh_b = smem_u32(Qhs), ql_b = smem_u32(Qls);
    const uint32_t kh_b = smem_u32(Khs), kl_b = smem_u32(Kls);
    const uint32_t vh_b = smem_u32(Vhs), vl_b = smem_u32(Vls);

    // prologue: KV tile 0
    {
        for (int idx = tid; idx < FN * 12; idx += 256) {
            int rr = idx / 12, c8 = (idx % 12) * 8;
            const int src = rr * D_ + c8;
            const uint32_t doff = (uint32_t)((rr * KSTR + c8) * 2);
            cp16(kh_b + doff, Kh + src);
            cp16(kl_b + doff, Kl + src);
            cp16(vh_b + doff, Vh + src);
            cp16(vl_b + doff, Vl + src);
        }
        cp_commit();
    }
    for (int idx = tid; idx < FM * 12; idx += 256) {
        int rr = idx / 12, c8 = (idx % 12) * 8;
        *(uint4*)&Qhs[rr * KSTR + c8] = *(const uint4*)&Qh[(qStart + rr) * D_ + c8];
        *(uint4*)&Qls[rr * KSTR + c8] = *(const uint4*)&Ql[(qStart + rr) * D_ + c8];
    }

    float O[12][4];
    #pragma unroll
    for (int d = 0; d < 12; d++)
        #pragma unroll
        for (int e = 0; e < 4; e++) O[d][e] = 0.f;
    float m0 = -INFINITY, m1 = -INFINITY, l0 = 0.f, l1 = 0.f;

    const int qrow_off = (16 * wid + lr) * KSTR + lc8;
    constexpr int NT = N_ / FN;

    for (int kt = 0; kt < NT; kt++) {
        const int p = kt & 1;
        if (kt + 1 < NT) {
            const uint32_t sbase = (uint32_t)((1 - p) * KVBUF * 2);
            for (int idx = tid; idx < FN * 12; idx += 256) {
                int rr = idx / 12, c8 = (idx % 12) * 8;
                const int src = ((kt + 1) * FN + rr) * D_ + c8;
                const uint32_t doff = sbase + (rr * KSTR + c8) * 2;
                cp16(kh_b + doff, Kh + src);
                cp16(kl_b + doff, Kl + src);
                cp16(vh_b + doff, Vh + src);
                cp16(vl_b + doff, Vl + src);
            }
            cp_commit();
            asm volatile("cp.async.wait_group 1;");
        } else {
            asm volatile("cp.async.wait_group 0;");
        }
        __syncthreads();

        const uint32_t kvoff = (uint32_t)(p * KVBUF * 2);

        float sa[8][4];
        #pragma unroll
        for (int nt = 0; nt < 8; nt++)
            #pragma unroll
            for (int e = 0; e < 4; e++) sa[nt][e] = 0.f;

        #pragma unroll
        for (int kc = 0; kc < 6; kc++) {
            uint32_t qa[4], qb[4];
            ldsm_x4(qa, qh_b + (qrow_off + kc * 16) * 2);
            ldsm_x4(qb, ql_b + (qrow_off + kc * 16) * 2);
            #pragma unroll
            for (int np = 0; np < 4; np++) {
                const uint32_t koff = kvoff + ((np * 16 + lr) * KSTR + kc * 16 + lc8) * 2;
                uint32_t ka[4], kb[4];
                ldsm_x4(ka, kh_b + koff);
                ldsm_x4(kb, kl_b + koff);
                mma16816(sa[2 * np],     qa, ka[0], ka[2]);
                mma16816(sa[2 * np],     qa, kb[0], kb[2]);
                mma16816(sa[2 * np],     qb, ka[0], ka[2]);
                mma16816(sa[2 * np + 1], qa, ka[1], ka[3]);
                mma16816(sa[2 * np + 1], qa, kb[1], kb[3]);
                mma16816(sa[2 * np + 1], qb, ka[1], ka[3]);
            }
        }

        float mx0 = -INFINITY, mx1 = -INFINITY;
        #pragma unroll
        for (int nt = 0; nt < 8; nt++) {
            mx0 = fmaxf(mx0, fmaxf(sa[nt][0], sa[nt][1]));
            mx1 = fmaxf(mx1, fmaxf(sa[nt][2], sa[nt][3]));
        }
        mx0 = fmaxf(mx0, __shfl_xor_sync(0xffffffffu, mx0, 1));
        mx0 = fmaxf(mx0, __shfl_xor_sync(0xffffffffu, mx0, 2));
        mx1 = fmaxf(mx1, __shfl_xor_sync(0xffffffffu, mx1, 1));
        mx1 = fmaxf(mx1, __shfl_xor_sync(0xffffffffu, mx1, 2));
        const float mn0 = fmaxf(m0, mx0), mn1 = fmaxf(m1, mx1);
        const float al0 = __expf(m0 - mn0), al1 = __expf(m1 - mn1);
        float ps0 = 0.f, ps1 = 0.f;
        #pragma unroll
        for (int nt = 0; nt < 8; nt++) {
            sa[nt][0] = __expf(sa[nt][0] - mn0); ps0 += sa[nt][0];
            sa[nt][1] = __expf(sa[nt][1] - mn0); ps0 += sa[nt][1];
            sa[nt][2] = __expf(sa[nt][2] - mn1); ps1 += sa[nt][2];
            sa[nt][3] = __expf(sa[nt][3] - mn1); ps1 += sa[nt][3];
        }
        ps0 += __shfl_xor_sync(0xffffffffu, ps0, 1);
        ps0 += __shfl_xor_sync(0xffffffffu, ps0, 2);
        ps1 += __shfl_xor_sync(0xffffffffu, ps1, 1);
        ps1 += __shfl_xor_sync(0xffffffffu, ps1, 2);
        l0 = l0 * al0 + ps0;  m0 = mn0;
        l1 = l1 * al1 + ps1;  m1 = mn1;
        #pragma unroll
        for (int d = 0; d < 12; d++) {
            O[d][0] *= al0;  O[d][1] *= al0;
            O[d][2] *= al1;  O[d][3] *= al1;
        }

        #pragma unroll
        for (int kc = 0; kc < 4; kc++) {
            uint32_t ah[4], alo[4];
            split2(sa[2 * kc][0],     sa[2 * kc][1],     ah[0], alo[0]);
            split2(sa[2 * kc][2],     sa[2 * kc][3],     ah[1], alo[1]);
            split2(sa[2 * kc + 1][0], sa[2 * kc + 1][1], ah[2], alo[2]);
            split2(sa[2 * kc + 1][2], sa[2 * kc + 1][3], ah[3], alo[3]);
            #pragma unroll
            for (int dp = 0; dp < 6; dp++) {
                const uint32_t voff = kvoff + ((kc * 16 + lr) * KSTR + dp * 16 + lc8) * 2;
                uint32_t va[4], vb[4];
                ldsm_x4_t(va, vh_b + voff);
                ldsm_x4_t(vb, vl_b + voff);
                mma16816(O[2 * dp],     ah,  va[0], va[1]);
                mma16816(O[2 * dp],     ah,  vb[0], vb[1]);
                mma16816(O[2 * dp],     alo, va[0], va[1]);
                mma16816(O[2 * dp + 1], ah,  va[2], va[3]);
                mma16816(O[2 * dp + 1], ah,  vb[2], vb[3]);
                mma16816(O[2 * dp + 1], alo, va[2], va[3]);
            }
        }
        __syncthreads();
    }

    // epilogue: /(l*sqrt(D)), merge heads, emit bf16 hi/lo g_att
    const float inv0 = 1.0f / (l0 * SCALING_);
    const float inv1 = 1.0f / (l1 * SCALING_);
    const int bb = bh >> 3, hh = bh & 7;
    const int r0g = qStart + 16 * wid + (lane >> 2);
    const int cbase = hh * D_ + 2 * (lane & 3);
    #pragma unroll
    for (int dt = 0; dt < 12; dt++) {
        const int c = cbase + dt * 8;
        uint32_t h0, l0u, h1, l1u;
        split2(O[dt][0] * inv0, O[dt][1] * inv0, h0, l0u);
        split2(O[dt][2] * inv1, O[dt][3] * inv1, h1, l1u);
        const size_t o0 = ((size_t)bb * N_ + r0g) * E_ + c;
        const size_t o1 = ((size_t)bb * N_ + r0g + 8) * E_ + c;
        *(uint32_t*)&g_att_hi[o0] = h0;
        *(uint32_t*)&g_att_lo[o0] = l0u;
        *(uint32_t*)&g_att_hi[o1] = h1;
        *(uint32_t*)&g_att_lo[o1] = l1u;
    }
}

// ---------------------------------------------------------------------------
extern "C" void kernel_launch(void* const* d_in, const int* in_sizes, int n_in,
                              void* d_out, int out_size)
{
    const float* x  = (const float*)d_in[0];
    const float* Wq = (const float*)d_in[1];
    const float* bq = (const float*)d_in[2];
    const float* Wk = (const float*)d_in[3];
    const float* bk = (const float*)d_in[4];
    const float* Wv = (const float*)d_in[5];
    const float* bv = (const float*)d_in[6];
    const float* Wo = (const float*)d_in[7];
    const float* bo = (const float*)d_in[8];
    float* out = (float*)d_out;

    __nv_bfloat16 *xh, *xl, *wqh, *wql, *wkh, *wkl, *wvh, *wvl, *woh, *wol;
    cudaGetSymbolAddress((void**)&xh,  g_x_hi);   cudaGetSymbolAddress((void**)&xl,  g_x_lo);
    cudaGetSymbolAddress((void**)&wqh, g_wq_hi);  cudaGetSymbolAddress((void**)&wql, g_wq_lo);
    cudaGetSymbolAddress((void**)&wkh, g_wk_hi);  cudaGetSymbolAddress((void**)&wkl, g_wk_lo);
    cudaGetSymbolAddress((void**)&wvh, g_wv_hi);  cudaGetSymbolAddress((void**)&wvl, g_wv_lo);
    cudaGetSymbolAddress((void**)&woh, g_wo_hi);  cudaGetSymbolAddress((void**)&wol, g_wo_lo);

    // Split inputs to bf16 hi/lo
    const int xn4 = M_ * E_ / 4, wn4 = E_ * E_ / 4;
    split_f32<<<(xn4 + 255) / 256, 256>>>(x,  xh,  xl,  xn4);
    split_f32<<<(wn4 + 255) / 256, 256>>>(Wq, wqh, wql, wn4);
    split_f32<<<(wn4 + 255) / 256, 256>>>(Wk, wkh, wkl, wn4);
    split_f32<<<(wn4 + 255) / 256, 256>>>(Wv, wvh, wvl, wn4);
    split_f32<<<(wn4 + 255) / 256, 256>>>(Wo, woh, wol, wn4);

    cudaFuncSetAttribute(qkv_mma, cudaFuncAttributeMaxDynamicSharedMemorySize, SMEM_GEMM);
    cudaFuncSetAttribute(out_mma, cudaFuncAttributeMaxDynamicSharedMemorySize, SMEM_GEMM);
    cudaFuncSetAttribute(flash_attn_mma, cudaFuncAttributeMaxDynamicSharedMemorySize, SMEM_MMA);

    dim3 gQKV(M_ / 128, E_ / 128, 3);
    qkv_mma<<<gQKV, 256, SMEM_GEMM>>>(bq, bk, bv);

    dim3 gF(N_ / FM, B_ * H_);
    flash_attn_mma<<<gF, 256, SMEM_MMA>>>();

    dim3 gO(M_ / 128, E_ / 128);
    out_mma<<<gO, 256, SMEM_GEMM>>>(bo, out);
}